// round 10
// baseline (speedup 1.0000x reference)
#include <cuda_runtime.h>

#define B_   32
#define T_   256
#define F_   64
#define C_   16
#define CO_  16
#define P_   64
#define S_   32
#define K_   4
#define FC   1024
#define KIN  1056
#define OUTC 96
#define ROWS (B_*T_)        // 8192
#define RSTR (F_*OUTC)      // 6144 floats per (b,t) row

// split-K4 partial sums (no bias/relu): 4 x 8192 x 64 fp32 = 8 MB
__device__ __align__(256) float g_part[4][ROWS][P_];

// ---------------- packed f32x2 helpers ----------------
__device__ __forceinline__ double pack2(float lo, float hi) {
    double d; asm("mov.b64 %0, {%1, %2};" : "=d"(d) : "f"(lo), "f"(hi)); return d;
}
__device__ __forceinline__ float2 unpack2(double d) {
    float2 v; asm("mov.b64 {%0, %1}, %2;" : "=f"(v.x), "=f"(v.y) : "d"(d)); return v;
}
__device__ __forceinline__ void fma2(double& acc, double a, double b) {
    asm("fma.rn.f32x2 %0, %1, %2, %3;" : "=d"(acc) : "d"(a), "d"(b), "d"(acc));
}

struct SmemG {                                  // gemm role: ~25 KB
    alignas(16) double Ad[32][66];              // [kk][m] dup doubles (BM=64)
    alignas(16) float  Bsf[32][64];             // [kk][n] natural pairs
};
struct SmemC {                                  // conv role: ~23 KB
    alignas(16) float xs[T_ + 6][17];
    alignas(16) float ws[64][20];
    alignas(16) float bsv[16];
};
union SmemU { SmemG g; SmemC c; };

// ============================================================================
// K1: blockIdx%5==0 -> split-K4 GEMM (512 blocks: 128 tiles x 4 K-quarters,
//     BM=64, BN=64, BK=32, per-thread 4m x 4n) -> g_part[quarter].
//     else -> conv per (b,f) (2048 blocks): ch16..31 + relu(x) ch0..15.
// ============================================================================
__global__ __launch_bounds__(256)
void tpc_main(const float* __restrict__ x,
              const float* __restrict__ stat,
              const float* __restrict__ conv_w,
              const float* __restrict__ conv_b,
              const float* __restrict__ W_p,
              float* __restrict__ out)
{
    __shared__ SmemU sm;
    const int tid  = threadIdx.x;
    const int grp  = blockIdx.x / 5;
    const int role = blockIdx.x - grp * 5;

    if (role == 0) {
        // ======================= GEMM ROLE =======================
        const int tile    = grp >> 2;           // 0..127
        const int quarter = grp & 3;
        const int row0    = tile * 64;
        const int b       = row0 >> 8;

        const int kb0 = (quarter == 0) ? 0 : (9 + 8 * (quarter - 1));   // {0,9,17,25}
        const int kbE = 9 + 8 * quarter;                                 // {9,17,25,33}

        const int m0 = (tid >> 4) * 4;
        const int n0 = (tid & 15) * 4;
        const int akq = tid & 7;

        double acc[4][2];
        #pragma unroll
        for (int i = 0; i < 4; ++i) { acc[i][0] = 0.0; acc[i][1] = 0.0; }

        float4 pa[2], pb[2];

        // prefetch first tile (kb0*32 + 31 < 1024 for all quarters -> x only)
        #pragma unroll
        for (int l = 0; l < 2; ++l) {
            int idx = tid + l * 256;
            int r   = idx >> 3;
            pa[l] = *reinterpret_cast<const float4*>(
                &x[(size_t)(row0 + r) * FC + kb0 * 32 + (idx & 7) * 4]);
        }
        #pragma unroll
        for (int l = 0; l < 2; ++l) {
            int idx = tid + l * 256;
            pb[l] = *reinterpret_cast<const float4*>(
                &W_p[(size_t)(kb0 * 32 + (idx >> 4)) * P_ + (idx & 15) * 4]);
        }

        for (int kb = kb0; kb < kbE; ++kb) {
            #pragma unroll
            for (int l = 0; l < 2; ++l) {
                int idx = tid + l * 256;
                int r   = idx >> 3;
                int kq  = idx & 7;
                sm.g.Ad[kq * 4 + 0][r] = pack2(pa[l].x, pa[l].x);
                sm.g.Ad[kq * 4 + 1][r] = pack2(pa[l].y, pa[l].y);
                sm.g.Ad[kq * 4 + 2][r] = pack2(pa[l].z, pa[l].z);
                sm.g.Ad[kq * 4 + 3][r] = pack2(pa[l].w, pa[l].w);
            }
            #pragma unroll
            for (int l = 0; l < 2; ++l) {
                int idx = tid + l * 256;
                *reinterpret_cast<float4*>(&sm.g.Bsf[idx >> 4][(idx & 15) * 4]) = pb[l];
            }
            __syncthreads();

            if (kb + 1 < kbE) {
                int kg0 = (kb + 1) * 32;
                #pragma unroll
                for (int l = 0; l < 2; ++l) {
                    int idx = tid + l * 256;
                    int r   = idx >> 3;
                    int kgf = kg0 + (idx & 7) * 4;
                    if (kgf < FC)
                        pa[l] = *reinterpret_cast<const float4*>(&x[(size_t)(row0 + r) * FC + kgf]);
                    else
                        pa[l] = *reinterpret_cast<const float4*>(&stat[b * S_ + (kgf - FC)]);
                }
                #pragma unroll
                for (int l = 0; l < 2; ++l) {
                    int idx = tid + l * 256;
                    pb[l] = *reinterpret_cast<const float4*>(
                        &W_p[(size_t)(kg0 + (idx >> 4)) * P_ + (idx & 15) * 4]);
                }
            }

            #pragma unroll
            for (int kk = 0; kk < 32; ++kk) {
                double2 a01 = *reinterpret_cast<const double2*>(&sm.g.Ad[kk][m0]);
                double2 a23 = *reinterpret_cast<const double2*>(&sm.g.Ad[kk][m0 + 2]);
                double2 bp  = *reinterpret_cast<const double2*>(&sm.g.Bsf[kk][n0]);
                fma2(acc[0][0], a01.x, bp.x); fma2(acc[0][1], a01.x, bp.y);
                fma2(acc[1][0], a01.y, bp.x); fma2(acc[1][1], a01.y, bp.y);
                fma2(acc[2][0], a23.x, bp.x); fma2(acc[2][1], a23.x, bp.y);
                fma2(acc[3][0], a23.y, bp.x); fma2(acc[3][1], a23.y, bp.y);
            }
            __syncthreads();
        }

        // store raw partials
        #pragma unroll
        for (int m = 0; m < 4; ++m) {
            float2 p = unpack2(acc[m][0]);
            float2 q = unpack2(acc[m][1]);
            *reinterpret_cast<float4*>(&g_part[quarter][row0 + m0 + m][n0]) =
                make_float4(p.x, p.y, q.x, q.y);
        }
    } else {
        // ======================= CONV ROLE =======================
        const int cb = grp * 4 + (role - 1);    // 0..2047
        const int b  = cb >> 6;
        const int f  = cb & 63;
        const size_t xrow0 = ((size_t)b * T_ * F_ + f) * C_;

        #pragma unroll
        for (int l = 0; l < 5; ++l) {
            int idx = tid + l * 256;
            if (idx < (T_ + 6) * 4) {
                int r = idx >> 2;
                int q = idx & 3;
                float4 v = make_float4(0.f, 0.f, 0.f, 0.f);
                if (r >= 6)
                    v = *reinterpret_cast<const float4*>(&x[xrow0 + (size_t)(r - 6) * FC + q * 4]);
                sm.c.xs[r][q * 4 + 0] = v.x;
                sm.c.xs[r][q * 4 + 1] = v.y;
                sm.c.xs[r][q * 4 + 2] = v.z;
                sm.c.xs[r][q * 4 + 3] = v.w;
            }
        }
        {
            int co = tid >> 4;
            int c  = tid & 15;
            float4 w = *reinterpret_cast<const float4*>(&conv_w[((size_t)f * CO_ + co) * 64 + c * 4]);
            sm.c.ws[c * 4 + 0][co] = w.x;
            sm.c.ws[c * 4 + 1][co] = w.y;
            sm.c.ws[c * 4 + 2][co] = w.z;
            sm.c.ws[c * 4 + 3][co] = w.w;
        }
        if (tid < 16) sm.c.bsv[tid] = conv_b[f * CO_ + tid];
        __syncthreads();

        const int t0  = (tid >> 2) * 4;
        const int co0 = (tid & 3) * 4;

        double acc[4][2];
        #pragma unroll
        for (int i = 0; i < 4; ++i) { acc[i][0] = 0.0; acc[i][1] = 0.0; }

        #pragma unroll 4
        for (int c = 0; c < C_; ++c) {
            double ad[10];
            #pragma unroll
            for (int r = 0; r < 10; ++r) {
                float a = sm.c.xs[t0 + r][c];
                ad[r] = pack2(a, a);
            }
            #pragma unroll
            for (int k = 0; k < K_; ++k) {
                double2 w = *reinterpret_cast<const double2*>(&sm.c.ws[c * 4 + k][co0]);
                #pragma unroll
                for (int i = 0; i < 4; ++i) {
                    fma2(acc[i][0], ad[i + 2 * k], w.x);
                    fma2(acc[i][1], ad[i + 2 * k], w.y);
                }
            }
        }

        float* ob = out + ((size_t)b * T_ * F_ + f) * OUTC;

        // ch16..31 from registers
        {
            float4 bb = *reinterpret_cast<const float4*>(&sm.c.bsv[co0]);
            #pragma unroll
            for (int i = 0; i < 4; ++i) {
                float2 q0 = unpack2(acc[i][0]);
                float2 q1 = unpack2(acc[i][1]);
                float4 v = make_float4(fmaxf(q0.x + bb.x, 0.f), fmaxf(q0.y + bb.y, 0.f),
                                       fmaxf(q1.x + bb.z, 0.f), fmaxf(q1.y + bb.w, 0.f));
                *reinterpret_cast<float4*>(&ob[(size_t)(t0 + i) * RSTR + 16 + co0]) = v;
            }
        }

        // ch0..15 = relu(x) (L2-hot re-read, 1024 float4)
        #pragma unroll
        for (int l = 0; l < 4; ++l) {
            int idx = tid + l * 256;
            int t   = idx >> 2;
            int q   = idx & 3;
            float4 v = *reinterpret_cast<const float4*>(&x[xrow0 + (size_t)t * FC + q * 4]);
            v.x = fmaxf(v.x, 0.f); v.y = fmaxf(v.y, 0.f);
            v.z = fmaxf(v.z, 0.f); v.w = fmaxf(v.w, 0.f);
            *reinterpret_cast<float4*>(&ob[(size_t)t * RSTR + q * 4]) = v;
        }
    }
}

// ============================================================================
// K2: pure broadcast. ch32..95 = relu(sum of 4 K-partials + b_p), replicated
// across 64 features. 2048 blocks x 256 thr, 4 rows per block.
// ============================================================================
__global__ __launch_bounds__(256)
void tpc_bcast(const float* __restrict__ b_p, float* __restrict__ out)
{
    const int tid = threadIdx.x;
    const int q   = tid & 15;
    const int f0  = tid >> 4;
    const int row_base = blockIdx.x * 4;
    float4 bb = *reinterpret_cast<const float4*>(&b_p[q * 4]);

    #pragma unroll
    for (int rr = 0; rr < 4; ++rr) {
        int row = row_base + rr;
        float4 v0 = *reinterpret_cast<const float4*>(&g_part[0][row][q * 4]);
        float4 v1 = *reinterpret_cast<const float4*>(&g_part[1][row][q * 4]);
        float4 v2 = *reinterpret_cast<const float4*>(&g_part[2][row][q * 4]);
        float4 v3 = *reinterpret_cast<const float4*>(&g_part[3][row][q * 4]);
        float4 v;
        v.x = fmaxf((v0.x + v1.x) + (v2.x + v3.x) + bb.x, 0.f);
        v.y = fmaxf((v0.y + v1.y) + (v2.y + v3.y) + bb.y, 0.f);
        v.z = fmaxf((v0.z + v1.z) + (v2.z + v3.z) + bb.z, 0.f);
        v.w = fmaxf((v0.w + v1.w) + (v2.w + v3.w) + bb.w, 0.f);
        float* ob = out + (size_t)row * RSTR + 32 + q * 4;
        #pragma unroll
        for (int ff = 0; ff < 4; ++ff) {
            int f = ff * 16 + f0;
            *reinterpret_cast<float4*>(&ob[(size_t)f * OUTC]) = v;
        }
    }
}

extern "C" void kernel_launch(void* const* d_in, const int* in_sizes, int n_in,
                              void* d_out, int out_size)
{
    const float* x      = (const float*)d_in[0];   // [32,256,64,16]
    const float* statv  = (const float*)d_in[1];   // [32,32]
    const float* conv_w = (const float*)d_in[2];   // [64,16,16,4]
    const float* conv_b = (const float*)d_in[3];   // [64,16]
    const float* W_p    = (const float*)d_in[4];   // [1056,64]
    const float* b_p    = (const float*)d_in[5];   // [64]
    float* out = (float*)d_out;                    // [32,256,64,96]

    tpc_main<<<2560, 256>>>(x, statv, conv_w, conv_b, W_p, out);
    tpc_bcast<<<ROWS / 4, 256>>>(b_p, out);
}

// round 11
// speedup vs baseline: 1.0362x; 1.0362x over previous
#include <cuda_runtime.h>

#define B_   32
#define T_   256
#define F_   64
#define C_   16
#define CO_  16
#define P_   64
#define S_   32
#define K_   4
#define FC   1024
#define KIN  1056
#define OUTC 96
#define ROWS (B_*T_)        // 8192
#define RSTR (F_*OUTC)      // 6144 floats per (b,t) row

// split-K4 partial sums (no bias/relu): 4 x 8192 x 64 fp32 = 8 MB
__device__ __align__(256) float g_part[4][ROWS][P_];

// ---------------- packed f32x2 helpers ----------------
__device__ __forceinline__ double pack2(float lo, float hi) {
    double d; asm("mov.b64 %0, {%1, %2};" : "=d"(d) : "f"(lo), "f"(hi)); return d;
}
__device__ __forceinline__ float2 unpack2(double d) {
    float2 v; asm("mov.b64 {%0, %1}, %2;" : "=f"(v.x), "=f"(v.y) : "d"(d)); return v;
}
__device__ __forceinline__ void fma2(double& acc, double a, double b) {
    asm("fma.rn.f32x2 %0, %1, %2, %3;" : "=d"(acc) : "d"(a), "d"(b), "d"(acc));
}

// ============================================================================
// Kernel 1: split-K4 point GEMM. grid=1024 (256 tiles x 4 K-quarters), 128 thr.
// BM=32, BN=64, BK=32, per-thread 4m x 4n. Triggers PDL completion at start.
// quarters: kb [0,9) [9,17) [17,25) [25,33)
// ============================================================================
__global__ __launch_bounds__(128)
void tpc_gemm(const float* __restrict__ x,
              const float* __restrict__ stat,
              const float* __restrict__ W_p)
{
    cudaTriggerProgrammaticLaunchCompletion();

    __shared__ __align__(16) double Ad[32][34];   // [kk][m] dup doubles
    __shared__ __align__(16) float  Bsf[32][64];  // [kk][n] natural pairs

    const int tid     = threadIdx.x;
    const int tile    = blockIdx.x >> 2;
    const int quarter = blockIdx.x & 3;
    const int row0    = tile * 32;
    const int b       = row0 >> 8;

    const int kb0 = (quarter == 0) ? 0 : (9 + 8 * (quarter - 1));   // {0,9,17,25}
    const int kbE = 9 + 8 * quarter;                                 // {9,17,25,33}

    const int m0 = (tid >> 4) * 4;
    const int n0 = (tid & 15) * 4;
    const int akq = tid & 7;

    double acc[4][2];
    #pragma unroll
    for (int i = 0; i < 4; ++i) { acc[i][0] = 0.0; acc[i][1] = 0.0; }

    float4 pa[2], pb[4];

    // prefetch first tile (kb0*32 + 31 < 1024 for all quarters -> x only)
    #pragma unroll
    for (int l = 0; l < 2; ++l) {
        int idx = tid + l * 128;
        int r   = idx >> 3;
        pa[l] = *reinterpret_cast<const float4*>(
            &x[(size_t)(row0 + r) * FC + kb0 * 32 + akq * 4]);
    }
    #pragma unroll
    for (int l = 0; l < 4; ++l) {
        int idx = tid + l * 128;
        pb[l] = *reinterpret_cast<const float4*>(
            &W_p[(size_t)(kb0 * 32 + (idx >> 4)) * P_ + (idx & 15) * 4]);
    }

    for (int kb = kb0; kb < kbE; ++kb) {
        #pragma unroll
        for (int l = 0; l < 2; ++l) {
            int idx = tid + l * 128;
            int r   = idx >> 3;
            Ad[akq * 4 + 0][r] = pack2(pa[l].x, pa[l].x);
            Ad[akq * 4 + 1][r] = pack2(pa[l].y, pa[l].y);
            Ad[akq * 4 + 2][r] = pack2(pa[l].z, pa[l].z);
            Ad[akq * 4 + 3][r] = pack2(pa[l].w, pa[l].w);
        }
        #pragma unroll
        for (int l = 0; l < 4; ++l) {
            int idx = tid + l * 128;
            *reinterpret_cast<float4*>(&Bsf[idx >> 4][(idx & 15) * 4]) = pb[l];
        }
        __syncthreads();

        if (kb + 1 < kbE) {
            int kg0 = (kb + 1) * 32;
            #pragma unroll
            for (int l = 0; l < 2; ++l) {
                int idx = tid + l * 128;
                int r   = idx >> 3;
                int kgf = kg0 + akq * 4;
                if (kgf < FC)
                    pa[l] = *reinterpret_cast<const float4*>(&x[(size_t)(row0 + r) * FC + kgf]);
                else
                    pa[l] = *reinterpret_cast<const float4*>(&stat[b * S_ + (kgf - FC)]);
            }
            #pragma unroll
            for (int l = 0; l < 4; ++l) {
                int idx = tid + l * 128;
                pb[l] = *reinterpret_cast<const float4*>(
                    &W_p[(size_t)(kg0 + (idx >> 4)) * P_ + (idx & 15) * 4]);
            }
        }

        #pragma unroll
        for (int kk = 0; kk < 32; ++kk) {
            double2 a01 = *reinterpret_cast<const double2*>(&Ad[kk][m0]);
            double2 a23 = *reinterpret_cast<const double2*>(&Ad[kk][m0 + 2]);
            double2 bp  = *reinterpret_cast<const double2*>(&Bsf[kk][n0]);
            fma2(acc[0][0], a01.x, bp.x); fma2(acc[0][1], a01.x, bp.y);
            fma2(acc[1][0], a01.y, bp.x); fma2(acc[1][1], a01.y, bp.y);
            fma2(acc[2][0], a23.x, bp.x); fma2(acc[2][1], a23.x, bp.y);
            fma2(acc[3][0], a23.y, bp.x); fma2(acc[3][1], a23.y, bp.y);
        }
        __syncthreads();
    }

    #pragma unroll
    for (int m = 0; m < 4; ++m) {
        float2 p = unpack2(acc[m][0]);
        float2 q = unpack2(acc[m][1]);
        *reinterpret_cast<float4*>(&g_part[quarter][row0 + m0 + m][n0]) =
            make_float4(p.x, p.y, q.x, q.y);
    }
}

// ============================================================================
// Kernel 2 (PDL secondary): blocks [0,2048) conv -> ch16..31.
// blocks [2048,4096): relu(x) ch0..15 (independent preamble), then
// cudaGridDependencySynchronize(), then ch32..95 = relu(sum partials + b_p).
// ============================================================================
__global__ __launch_bounds__(256)
void tpc_fuse(const float* __restrict__ x,
              const float* __restrict__ conv_w,
              const float* __restrict__ conv_b,
              const float* __restrict__ b_p,
              float* __restrict__ out)
{
    __shared__ __align__(16) float xs[T_ + 6][17];
    __shared__ __align__(16) float ws[64][20];
    __shared__ float bsv[16];

    const int tid = threadIdx.x;

    if (blockIdx.x < 2048) {
        // ---------------- CONV ROLE (independent of gemm) ----------------
        const int cb = blockIdx.x;
        const int b  = cb >> 6;
        const int f  = cb & 63;
        const size_t xrow0 = ((size_t)b * T_ * F_ + f) * C_;

        #pragma unroll
        for (int l = 0; l < 5; ++l) {
            int idx = tid + l * 256;
            if (idx < (T_ + 6) * 4) {
                int r = idx >> 2;
                int q = idx & 3;
                float4 v = make_float4(0.f, 0.f, 0.f, 0.f);
                if (r >= 6)
                    v = *reinterpret_cast<const float4*>(&x[xrow0 + (size_t)(r - 6) * FC + q * 4]);
                xs[r][q * 4 + 0] = v.x;
                xs[r][q * 4 + 1] = v.y;
                xs[r][q * 4 + 2] = v.z;
                xs[r][q * 4 + 3] = v.w;
            }
        }
        {
            int co = tid >> 4;
            int c  = tid & 15;
            float4 w = *reinterpret_cast<const float4*>(&conv_w[((size_t)f * CO_ + co) * 64 + c * 4]);
            ws[c * 4 + 0][co] = w.x;
            ws[c * 4 + 1][co] = w.y;
            ws[c * 4 + 2][co] = w.z;
            ws[c * 4 + 3][co] = w.w;
        }
        if (tid < 16) bsv[tid] = conv_b[f * CO_ + tid];
        __syncthreads();

        const int t0  = (tid >> 2) * 4;
        const int co0 = (tid & 3) * 4;

        double acc[4][2];
        #pragma unroll
        for (int i = 0; i < 4; ++i) { acc[i][0] = 0.0; acc[i][1] = 0.0; }

        #pragma unroll 4
        for (int c = 0; c < C_; ++c) {
            double ad[10];
            #pragma unroll
            for (int r = 0; r < 10; ++r) {
                float a = xs[t0 + r][c];
                ad[r] = pack2(a, a);
            }
            #pragma unroll
            for (int k = 0; k < K_; ++k) {
                double2 w = *reinterpret_cast<const double2*>(&ws[c * 4 + k][co0]);
                #pragma unroll
                for (int i = 0; i < 4; ++i) {
                    fma2(acc[i][0], ad[i + 2 * k], w.x);
                    fma2(acc[i][1], ad[i + 2 * k], w.y);
                }
            }
        }

        float4 bb = *reinterpret_cast<const float4*>(&bsv[co0]);
        float* ob = out + ((size_t)b * T_ * F_ + f) * OUTC;
        #pragma unroll
        for (int i = 0; i < 4; ++i) {
            float2 q0 = unpack2(acc[i][0]);
            float2 q1 = unpack2(acc[i][1]);
            float4 v = make_float4(fmaxf(q0.x + bb.x, 0.f), fmaxf(q0.y + bb.y, 0.f),
                                   fmaxf(q1.x + bb.z, 0.f), fmaxf(q1.y + bb.w, 0.f));
            *reinterpret_cast<float4*>(&ob[(size_t)(t0 + i) * RSTR + 16 + co0]) = v;
        }
    } else {
        // ---------------- STREAM ROLE ----------------
        const int rb = blockIdx.x - 2048;
        const int row_base = rb * 4;

        // preamble (independent): ch 0..15 = relu(x)
        #pragma unroll
        for (int l = 0; l < 4; ++l) {
            int idx  = tid + l * 256;
            int r    = idx >> 8;
            int rest = idx & 255;
            int row  = row_base + r;
            float4 v = *reinterpret_cast<const float4*>(&x[(size_t)row * FC + rest * 4]);
            v.x = fmaxf(v.x, 0.f); v.y = fmaxf(v.y, 0.f);
            v.z = fmaxf(v.z, 0.f); v.w = fmaxf(v.w, 0.f);
            int f = rest >> 2;
            int q = rest & 3;
            *reinterpret_cast<float4*>(&out[(size_t)row * RSTR + f * OUTC + q * 4]) = v;
        }

        // wait for gemm grid completion (PDL dependency)
        cudaGridDependencySynchronize();

        // ch 32..95: sum 4 K-partials + bias + relu, broadcast
        const int q  = tid & 15;
        const int f0 = tid >> 4;
        float4 bb = *reinterpret_cast<const float4*>(&b_p[q * 4]);
        #pragma unroll
        for (int rr = 0; rr < 4; ++rr) {
            int row  = row_base + rr;
            float4 v0 = *reinterpret_cast<const float4*>(&g_part[0][row][q * 4]);
            float4 v1 = *reinterpret_cast<const float4*>(&g_part[1][row][q * 4]);
            float4 v2 = *reinterpret_cast<const float4*>(&g_part[2][row][q * 4]);
            float4 v3 = *reinterpret_cast<const float4*>(&g_part[3][row][q * 4]);
            float4 v;
            v.x = fmaxf((v0.x + v1.x) + (v2.x + v3.x) + bb.x, 0.f);
            v.y = fmaxf((v0.y + v1.y) + (v2.y + v3.y) + bb.y, 0.f);
            v.z = fmaxf((v0.z + v1.z) + (v2.z + v3.z) + bb.z, 0.f);
            v.w = fmaxf((v0.w + v1.w) + (v2.w + v3.w) + bb.w, 0.f);
            float* ob = out + (size_t)row * RSTR + 32 + q * 4;
            #pragma unroll
            for (int ff = 0; ff < 4; ++ff) {
                int f = ff * 16 + f0;
                *reinterpret_cast<float4*>(&ob[(size_t)f * OUTC]) = v;
            }
        }
    }
}

extern "C" void kernel_launch(void* const* d_in, const int* in_sizes, int n_in,
                              void* d_out, int out_size)
{
    const float* x      = (const float*)d_in[0];   // [32,256,64,16]
    const float* statv  = (const float*)d_in[1];   // [32,32]
    const float* conv_w = (const float*)d_in[2];   // [64,16,16,4]
    const float* conv_b = (const float*)d_in[3];   // [64,16]
    const float* W_p    = (const float*)d_in[4];   // [1056,64]
    const float* b_p    = (const float*)d_in[5];   // [64]
    float* out = (float*)d_out;                    // [32,256,64,96]

    // primary: GEMM (triggers PDL completion early)
    tpc_gemm<<<1024, 128>>>(x, statv, W_p);

    // secondary: fuse, launched with programmatic stream serialization so its
    // independent blocks overlap the GEMM; stream blocks gridDependencySync
    // before touching g_part.
    cudaLaunchConfig_t cfg = {};
    cfg.gridDim  = dim3(4096);
    cfg.blockDim = dim3(256);
    cfg.dynamicSmemBytes = 0;
    cfg.stream = 0;
    cudaLaunchAttribute attrs[1];
    attrs[0].id = cudaLaunchAttributeProgrammaticStreamSerialization;
    attrs[0].val.programmaticStreamSerializationAllowed = 1;
    cfg.attrs = attrs;
    cfg.numAttrs = 1;
    cudaLaunchKernelEx(&cfg, tpc_fuse, x, conv_w, conv_b, b_p, (float*)out);
}

// round 12
// speedup vs baseline: 1.0541x; 1.0173x over previous
#include <cuda_runtime.h>

#define B_   32
#define T_   256
#define F_   64
#define C_   16
#define CO_  16
#define P_   64
#define S_   32
#define K_   4
#define FC   1024
#define KIN  1056
#define OUTC 96
#define ROWS (B_*T_)        // 8192
#define RSTR (F_*OUTC)      // 6144 floats per (b,t) row

// split-K4 partial sums (no bias/relu): 4 x 8192 x 64 fp32 = 8 MB
__device__ __align__(256) float g_part[4][ROWS][P_];

// ---------------- packed f32x2 helpers ----------------
__device__ __forceinline__ double pack2(float lo, float hi) {
    double d; asm("mov.b64 %0, {%1, %2};" : "=d"(d) : "f"(lo), "f"(hi)); return d;
}
__device__ __forceinline__ float2 unpack2(double d) {
    float2 v; asm("mov.b64 {%0, %1}, %2;" : "=f"(v.x), "=f"(v.y) : "d"(d)); return v;
}
__device__ __forceinline__ void fma2(double& acc, double a, double b) {
    asm("fma.rn.f32x2 %0, %1, %2, %3;" : "=d"(acc) : "d"(a), "d"(b), "d"(acc));
}

// ============================================================================
// Kernel 1: split-K4 point GEMM, double-buffered (ONE sync per kb-iter).
// grid=1024 (256 tiles x 4 K-quarters), 128 thr. BM=32, BN=64, BK=32.
// Per-thread 4m x 4n: 3 LDS.128 : 8 FMA2 per kk.
// ============================================================================
__global__ __launch_bounds__(128)
void tpc_gemm(const float* __restrict__ x,
              const float* __restrict__ stat,
              const float* __restrict__ W_p)
{
    __shared__ __align__(16) double Ad[2][32][34];   // dup-double A, 2 bufs
    __shared__ __align__(16) float  Bsf[2][32][64];  // natural-pair B, 2 bufs

    const int tid     = threadIdx.x;
    const int tile    = blockIdx.x >> 2;
    const int quarter = blockIdx.x & 3;
    const int row0    = tile * 32;
    const int b       = row0 >> 8;

    const int kb0 = (quarter == 0) ? 0 : (9 + 8 * (quarter - 1));   // {0,9,17,25}
    const int kbE = 9 + 8 * quarter;                                 // {9,17,25,33}

    const int m0  = (tid >> 4) * 4;
    const int n0  = (tid & 15) * 4;
    const int akq = tid & 7;

    double acc[4][2];
    #pragma unroll
    for (int i = 0; i < 4; ++i) { acc[i][0] = 0.0; acc[i][1] = 0.0; }

    float4 pa[2], pb[4];

    // load tile kb0 (kb0*32+31 < 1024 for all quarters -> x only) into buf 0
    #pragma unroll
    for (int l = 0; l < 2; ++l) {
        int idx = tid + l * 128;
        int r   = idx >> 3;
        pa[l] = *reinterpret_cast<const float4*>(
            &x[(size_t)(row0 + r) * FC + kb0 * 32 + akq * 4]);
    }
    #pragma unroll
    for (int l = 0; l < 4; ++l) {
        int idx = tid + l * 128;
        pb[l] = *reinterpret_cast<const float4*>(
            &W_p[(size_t)(kb0 * 32 + (idx >> 4)) * P_ + (idx & 15) * 4]);
    }
    #pragma unroll
    for (int l = 0; l < 2; ++l) {
        int idx = tid + l * 128;
        int r   = idx >> 3;
        Ad[0][akq * 4 + 0][r] = pack2(pa[l].x, pa[l].x);
        Ad[0][akq * 4 + 1][r] = pack2(pa[l].y, pa[l].y);
        Ad[0][akq * 4 + 2][r] = pack2(pa[l].z, pa[l].z);
        Ad[0][akq * 4 + 3][r] = pack2(pa[l].w, pa[l].w);
    }
    #pragma unroll
    for (int l = 0; l < 4; ++l) {
        int idx = tid + l * 128;
        *reinterpret_cast<float4*>(&Bsf[0][idx >> 4][(idx & 15) * 4]) = pb[l];
    }
    __syncthreads();

    int cur = 0;
    for (int kb = kb0; kb < kbE; ++kb) {
        const bool has_next = (kb + 1 < kbE);
        // issue prefetch LDGs for tile kb+1 (latency hidden by compute)
        if (has_next) {
            int kg0 = (kb + 1) * 32;
            #pragma unroll
            for (int l = 0; l < 2; ++l) {
                int idx = tid + l * 128;
                int r   = idx >> 3;
                int kgf = kg0 + akq * 4;
                if (kgf < FC)
                    pa[l] = *reinterpret_cast<const float4*>(&x[(size_t)(row0 + r) * FC + kgf]);
                else
                    pa[l] = *reinterpret_cast<const float4*>(&stat[b * S_ + (kgf - FC)]);
            }
            #pragma unroll
            for (int l = 0; l < 4; ++l) {
                int idx = tid + l * 128;
                pb[l] = *reinterpret_cast<const float4*>(
                    &W_p[(size_t)(kg0 + (idx >> 4)) * P_ + (idx & 15) * 4]);
            }
        }

        // compute from buf[cur]
        #pragma unroll
        for (int kk = 0; kk < 32; ++kk) {
            double2 a01 = *reinterpret_cast<const double2*>(&Ad[cur][kk][m0]);
            double2 a23 = *reinterpret_cast<const double2*>(&Ad[cur][kk][m0 + 2]);
            double2 bp  = *reinterpret_cast<const double2*>(&Bsf[cur][kk][n0]);
            fma2(acc[0][0], a01.x, bp.x); fma2(acc[0][1], a01.x, bp.y);
            fma2(acc[1][0], a01.y, bp.x); fma2(acc[1][1], a01.y, bp.y);
            fma2(acc[2][0], a23.x, bp.x); fma2(acc[2][1], a23.x, bp.y);
            fma2(acc[3][0], a23.y, bp.x); fma2(acc[3][1], a23.y, bp.y);
        }

        // store next tile into the other buffer (no reader conflict), then sync
        if (has_next) {
            int nxt = cur ^ 1;
            #pragma unroll
            for (int l = 0; l < 2; ++l) {
                int idx = tid + l * 128;
                int r   = idx >> 3;
                Ad[nxt][akq * 4 + 0][r] = pack2(pa[l].x, pa[l].x);
                Ad[nxt][akq * 4 + 1][r] = pack2(pa[l].y, pa[l].y);
                Ad[nxt][akq * 4 + 2][r] = pack2(pa[l].z, pa[l].z);
                Ad[nxt][akq * 4 + 3][r] = pack2(pa[l].w, pa[l].w);
            }
            #pragma unroll
            for (int l = 0; l < 4; ++l) {
                int idx = tid + l * 128;
                *reinterpret_cast<float4*>(&Bsf[nxt][idx >> 4][(idx & 15) * 4]) = pb[l];
            }
            __syncthreads();
            cur = nxt;
        }
    }

    #pragma unroll
    for (int m = 0; m < 4; ++m) {
        float2 p = unpack2(acc[m][0]);
        float2 q = unpack2(acc[m][1]);
        *reinterpret_cast<float4*>(&g_part[quarter][row0 + m0 + m][n0]) =
            make_float4(p.x, p.y, q.x, q.y);
    }
}

// ============================================================================
// Kernel 2: interleaved roles. even blocks: conv (b,f) -> out ch16..31.
// odd blocks: stream ch0..15 (relu x) + ch32..95 (sum partials + bias + relu).
// launch_bounds(256,4): clamp regs to 64 -> 4 CTAs/SM.
// ============================================================================
__global__ __launch_bounds__(256, 4)
void tpc_fuse(const float* __restrict__ x,
              const float* __restrict__ conv_w,
              const float* __restrict__ conv_b,
              const float* __restrict__ b_p,
              float* __restrict__ out)
{
    __shared__ __align__(16) float xs[T_ + 6][17];
    __shared__ __align__(16) float ws[64][20];
    __shared__ float bsv[16];

    const int tid = threadIdx.x;

    if ((blockIdx.x & 1) == 0) {
        // ---------------- CONV ROLE ----------------
        const int cb = blockIdx.x >> 1;
        const int b  = cb >> 6;
        const int f  = cb & 63;
        const size_t xrow0 = ((size_t)b * T_ * F_ + f) * C_;

        #pragma unroll
        for (int l = 0; l < 5; ++l) {
            int idx = tid + l * 256;
            if (idx < (T_ + 6) * 4) {
                int r = idx >> 2;
                int q = idx & 3;
                float4 v = make_float4(0.f, 0.f, 0.f, 0.f);
                if (r >= 6)
                    v = *reinterpret_cast<const float4*>(&x[xrow0 + (size_t)(r - 6) * FC + q * 4]);
                xs[r][q * 4 + 0] = v.x;
                xs[r][q * 4 + 1] = v.y;
                xs[r][q * 4 + 2] = v.z;
                xs[r][q * 4 + 3] = v.w;
            }
        }
        {
            int co = tid >> 4;
            int c  = tid & 15;
            float4 w = *reinterpret_cast<const float4*>(&conv_w[((size_t)f * CO_ + co) * 64 + c * 4]);
            ws[c * 4 + 0][co] = w.x;
            ws[c * 4 + 1][co] = w.y;
            ws[c * 4 + 2][co] = w.z;
            ws[c * 4 + 3][co] = w.w;
        }
        if (tid < 16) bsv[tid] = conv_b[f * CO_ + tid];
        __syncthreads();

        const int t0  = (tid >> 2) * 4;
        const int co0 = (tid & 3) * 4;

        double acc[4][2];
        #pragma unroll
        for (int i = 0; i < 4; ++i) { acc[i][0] = 0.0; acc[i][1] = 0.0; }

        #pragma unroll 4
        for (int c = 0; c < C_; ++c) {
            double ad[10];
            #pragma unroll
            for (int r = 0; r < 10; ++r) {
                float a = xs[t0 + r][c];
                ad[r] = pack2(a, a);
            }
            #pragma unroll
            for (int k = 0; k < K_; ++k) {
                double2 w = *reinterpret_cast<const double2*>(&ws[c * 4 + k][co0]);
                #pragma unroll
                for (int i = 0; i < 4; ++i) {
                    fma2(acc[i][0], ad[i + 2 * k], w.x);
                    fma2(acc[i][1], ad[i + 2 * k], w.y);
                }
            }
        }

        float4 bb = *reinterpret_cast<const float4*>(&bsv[co0]);
        float* ob = out + ((size_t)b * T_ * F_ + f) * OUTC;
        #pragma unroll
        for (int i = 0; i < 4; ++i) {
            float2 q0 = unpack2(acc[i][0]);
            float2 q1 = unpack2(acc[i][1]);
            float4 v = make_float4(fmaxf(q0.x + bb.x, 0.f), fmaxf(q0.y + bb.y, 0.f),
                                   fmaxf(q1.x + bb.z, 0.f), fmaxf(q1.y + bb.w, 0.f));
            *reinterpret_cast<float4*>(&ob[(size_t)(t0 + i) * RSTR + 16 + co0]) = v;
        }
    } else {
        // ---------------- STREAM ROLE ----------------
        const int rb = blockIdx.x >> 1;
        const int row_base = rb * 4;

        // ch 0..15: relu(x) (1024 float4)
        #pragma unroll
        for (int l = 0; l < 4; ++l) {
            int idx  = tid + l * 256;
            int r    = idx >> 8;
            int rest = idx & 255;
            int row  = row_base + r;
            float4 v = *reinterpret_cast<const float4*>(&x[(size_t)row * FC + rest * 4]);
            v.x = fmaxf(v.x, 0.f); v.y = fmaxf(v.y, 0.f);
            v.z = fmaxf(v.z, 0.f); v.w = fmaxf(v.w, 0.f);
            int f = rest >> 2;
            int q = rest & 3;
            *reinterpret_cast<float4*>(&out[(size_t)row * RSTR + f * OUTC + q * 4]) = v;
        }
        // ch 32..95: sum 4 K-partials + bias + relu, broadcast (4096 float4)
        const int q  = tid & 15;
        const int f0 = tid >> 4;
        float4 bb = *reinterpret_cast<const float4*>(&b_p[q * 4]);
        #pragma unroll
        for (int rr = 0; rr < 4; ++rr) {
            int row  = row_base + rr;
            float4 v0 = *reinterpret_cast<const float4*>(&g_part[0][row][q * 4]);
            float4 v1 = *reinterpret_cast<const float4*>(&g_part[1][row][q * 4]);
            float4 v2 = *reinterpret_cast<const float4*>(&g_part[2][row][q * 4]);
            float4 v3 = *reinterpret_cast<const float4*>(&g_part[3][row][q * 4]);
            float4 v;
            v.x = fmaxf((v0.x + v1.x) + (v2.x + v3.x) + bb.x, 0.f);
            v.y = fmaxf((v0.y + v1.y) + (v2.y + v3.y) + bb.y, 0.f);
            v.z = fmaxf((v0.z + v1.z) + (v2.z + v3.z) + bb.z, 0.f);
            v.w = fmaxf((v0.w + v1.w) + (v2.w + v3.w) + bb.w, 0.f);
            float* ob = out + (size_t)row * RSTR + 32 + q * 4;
            #pragma unroll
            for (int ff = 0; ff < 4; ++ff) {
                int f = ff * 16 + f0;
                *reinterpret_cast<float4*>(&ob[(size_t)f * OUTC]) = v;
            }
        }
    }
}

extern "C" void kernel_launch(void* const* d_in, const int* in_sizes, int n_in,
                              void* d_out, int out_size)
{
    const float* x      = (const float*)d_in[0];   // [32,256,64,16]
    const float* statv  = (const float*)d_in[1];   // [32,32]
    const float* conv_w = (const float*)d_in[2];   // [64,16,16,4]
    const float* conv_b = (const float*)d_in[3];   // [64,16]
    const float* W_p    = (const float*)d_in[4];   // [1056,64]
    const float* b_p    = (const float*)d_in[5];   // [64]
    float* out = (float*)d_out;                    // [32,256,64,96]

    tpc_gemm<<<1024, 128>>>(x, statv, W_p);
    tpc_fuse<<<4096, 256>>>(x, conv_w, conv_b, b_p, out);
}